// round 1
// baseline (speedup 1.0000x reference)
#include <cuda_runtime.h>
#include <cuda_bf16.h>
#include <math.h>

// Problem constants
#define BB   128          // batch
#define TT   20           // time steps
#define DIN  200
#define HH   1024
#define LL   12
#define NOUT 1095

// Scratch (device globals; no allocation allowed)
__device__ float g_h[TT * BB * HH];          // [T,B,H] layer activations (2,621,440 floats)
__device__ float g_U[TT * BB * 3 * HH];      // [T*B, 3H] SRU pre-activations (7,864,320 floats)

// ---------------------------------------------------------------------------
// SGEMM: C[M,N] = A'[M,K] @ W[K,N] (+ bias), where A' row m maps to A row
// perm(m).  PERM: 0 identity, 1: (m%B)*T + m/B  (x [B,T]->[T,B] order),
//                 2: (m%T)*B + m/T  ([T,B]->[B,T] order).
// RELU_A applies relu to A elements on load. VEC_B=false handles N%4 != 0.
// Requires: M % 128 == 0, K % 8 == 0.
// ---------------------------------------------------------------------------
template<int PERM, bool RELU_A, bool VEC_B>
__global__ __launch_bounds__(256)
void sgemm128(const float* __restrict__ A, const float* __restrict__ W,
              const float* __restrict__ bias, float* __restrict__ C,
              int M, int N, int K)
{
    const int BM = 128, BN = 128, BK = 8, TM = 8, TN = 8;
    __shared__ float As[BK][BM];
    __shared__ float Bs[BK][BN];

    const int bm  = blockIdx.y * BM;
    const int bn  = blockIdx.x * BN;
    const int tid = threadIdx.x;

    const int tx = (tid % 16) * TN;   // col offset within BN
    const int ty = (tid / 16) * TM;   // row offset within BM

    // A tile loader: 128x8 = 256 float4; thread -> row tid>>1, kof (tid&1)*4
    const int a_row = tid >> 1;
    const int a_kof = (tid & 1) * 4;
    // B tile loader: 8x128 = 256 float4; thread -> row tid>>5, col (tid&31)*4
    const int b_row = tid >> 5;
    const int b_col = (tid & 31) * 4;

    int gm = bm + a_row;
    int arow_g;
    if (PERM == 0)      arow_g = gm;
    else if (PERM == 1) arow_g = (gm % BB) * TT + (gm / BB);
    else                arow_g = (gm % TT) * BB + (gm / TT);
    const float* Aptr = A + (long)arow_g * K + a_kof;

    float acc[TM][TN];
#pragma unroll
    for (int i = 0; i < TM; i++)
#pragma unroll
        for (int j = 0; j < TN; j++) acc[i][j] = 0.f;

    for (int k0 = 0; k0 < K; k0 += BK) {
        // load A tile
        float4 av = *(const float4*)(Aptr + k0);
        if (RELU_A) {
            av.x = fmaxf(av.x, 0.f); av.y = fmaxf(av.y, 0.f);
            av.z = fmaxf(av.z, 0.f); av.w = fmaxf(av.w, 0.f);
        }
        As[a_kof + 0][a_row] = av.x;
        As[a_kof + 1][a_row] = av.y;
        As[a_kof + 2][a_row] = av.z;
        As[a_kof + 3][a_row] = av.w;

        // load B tile
        if (VEC_B) {
            float4 bv = *(const float4*)(W + (long)(k0 + b_row) * N + bn + b_col);
            *(float4*)&Bs[b_row][b_col] = bv;
        } else {
#pragma unroll
            for (int q = 0; q < 4; q++) {
                int col = bn + b_col + q;
                Bs[b_row][b_col + q] =
                    (col < N) ? W[(long)(k0 + b_row) * N + col] : 0.f;
            }
        }
        __syncthreads();

#pragma unroll
        for (int kk = 0; kk < BK; kk++) {
            float a_reg[TM], b_reg[TN];
#pragma unroll
            for (int i = 0; i < TM; i++) a_reg[i] = As[kk][ty + i];
#pragma unroll
            for (int j = 0; j < TN; j++) b_reg[j] = Bs[kk][tx + j];
#pragma unroll
            for (int i = 0; i < TM; i++)
#pragma unroll
                for (int j = 0; j < TN; j++)
                    acc[i][j] = fmaf(a_reg[i], b_reg[j], acc[i][j]);
        }
        __syncthreads();
    }

    // epilogue
#pragma unroll
    for (int i = 0; i < TM; i++) {
        int row = bm + ty + i;
#pragma unroll
        for (int j = 0; j < TN; j++) {
            int col = bn + tx + j;
            if (col < N) {
                float bv = bias ? bias[col] : 0.f;
                C[(long)row * N + col] = acc[i][j] + bv;
            }
        }
    }
}

// ---------------------------------------------------------------------------
// SRU elementwise scan for one layer.
// U     : [T*B, 3H]  (row m = t*B+b; cols: [x_tilde | f_pre | r_pre])
// b_l   : [2H]       (b_f | b_r)
// c0    : [B,H]      initial cell state for this layer
// h     : [T,B,H]    in: layer input (x_in); out: layer output (in-place)
// c_out : [B,H]      final cell state -> hidden_after[l]
// ---------------------------------------------------------------------------
__global__ __launch_bounds__(256)
void sru_scan(const float* __restrict__ U, const float* __restrict__ b_l,
              const float* __restrict__ c0, float* __restrict__ h,
              float* __restrict__ c_out)
{
    int idx = blockIdx.x * blockDim.x + threadIdx.x;
    if (idx >= BB * HH) return;
    int j = idx & (HH - 1);
    int b = idx >> 10;

    float bf = b_l[j];
    float br = b_l[HH + j];
    float c  = c0[idx];

#pragma unroll
    for (int t = 0; t < TT; t++) {
        long m = (long)t * BB + b;
        const float* u = U + m * (3 * HH);
        float xt   = u[j];
        float fpre = u[HH + j];
        float rpre = u[2 * HH + j];
        float f = 1.f / (1.f + __expf(-(fpre + bf)));
        float r = 1.f / (1.f + __expf(-(rpre + br)));
        long  hi = m * HH + j;
        float xin = h[hi];
        c = f * c + (1.f - f) * xt;
        h[hi] = r * tanhf(c) + (1.f - r) * xin;
    }
    c_out[idx] = c;
}

// ---------------------------------------------------------------------------
// kernel_launch
// Inputs (metadata order): x, hidden, W1, b1, sru_W, sru_b, W3, b3, W4, b4
// Output: [ logits (2560*1095) | fx (2560*1024) | hidden_after (12*128*1024) ]
// ---------------------------------------------------------------------------
extern "C" void kernel_launch(void* const* d_in, const int* in_sizes, int n_in,
                              void* d_out, int out_size)
{
    const float* x      = (const float*)d_in[0];
    const float* hidden = (const float*)d_in[1];
    const float* W1     = (const float*)d_in[2];
    const float* b1     = (const float*)d_in[3];
    const float* sru_W  = (const float*)d_in[4];
    const float* sru_b  = (const float*)d_in[5];
    const float* W3     = (const float*)d_in[6];
    const float* b3     = (const float*)d_in[7];
    const float* W4     = (const float*)d_in[8];
    const float* b4     = (const float*)d_in[9];

    float* out = (float*)d_out;
    const long M = (long)BB * TT;                 // 2560
    float* logits_out = out;                      // [2560, 1095]
    float* fx_out     = out + M * NOUT;           // [2560, 1024]
    float* hid_out    = fx_out + M * HH;          // [12, 128, 1024]

    float* hbuf; cudaGetSymbolAddress((void**)&hbuf, g_h);
    float* Ubuf; cudaGetSymbolAddress((void**)&Ubuf, g_U);

    dim3 blk(256);

    // 1) dense1: g_h[T,B,H] = x @ W1 + b1, with [B,T]->[T,B] row permute
    {
        dim3 grid(HH / 128, M / 128);
        sgemm128<1, false, true><<<grid, blk>>>(x, W1, b1, hbuf, (int)M, HH, DIN);
    }

    // 2) SRU layers
    for (int l = 0; l < LL; l++) {
        dim3 gridU(3 * HH / 128, M / 128);  // (24, 20)
        sgemm128<0, false, true><<<gridU, blk>>>(
            hbuf, sru_W + (long)l * HH * 3 * HH, nullptr, Ubuf,
            (int)M, 3 * HH, HH);

        int n = BB * HH;
        sru_scan<<<(n + 255) / 256, blk>>>(
            Ubuf, sru_b + (long)l * 2 * HH, hidden + (long)l * BB * HH,
            hbuf, hid_out + (long)l * BB * HH);
    }

    // 3) fx = h(reordered to [B*T]) @ W3 + b3
    {
        dim3 grid(HH / 128, M / 128);
        sgemm128<2, false, true><<<grid, blk>>>(hbuf, W3, b3, fx_out, (int)M, HH, HH);
    }

    // 4) logits = relu(fx) @ W4 + b4   (N=1095: scalar B loads + bounds)
    {
        dim3 grid((NOUT + 127) / 128, M / 128);  // (9, 20)
        sgemm128<0, true, false><<<grid, blk>>>(fx_out, W4, b4, logits_out,
                                                (int)M, NOUT, HH);
    }
}

// round 4
// speedup vs baseline: 2.5676x; 2.5676x over previous
#include <cuda_runtime.h>
#include <cuda_bf16.h>
#include <cstdint>
#include <math.h>

// Problem constants
#define BB   128
#define TT   20
#define DIN  200
#define HH   1024
#define LL   12
#define NOUT 1095
#define MM   (BB * TT)      // 2560
#define N3H  (3 * HH)       // 3072
#define NPAD4 1152          // W4 N padded to multiple of 128

// ---------------------------------------------------------------------------
// Scratch (device globals)
// ---------------------------------------------------------------------------
__device__ float g_h[TT * BB * HH];
__device__ float g_U[MM * N3H];
__device__ __nv_bfloat16 g_Ahi[MM * HH];
__device__ __nv_bfloat16 g_Alo[MM * HH];
__device__ __nv_bfloat16 g_Wt_hi[LL * N3H * HH];
__device__ __nv_bfloat16 g_Wt_lo[LL * N3H * HH];
__device__ __nv_bfloat16 g_W3t_hi[HH * HH];
__device__ __nv_bfloat16 g_W3t_lo[HH * HH];
__device__ __nv_bfloat16 g_W4t_hi[NPAD4 * HH];
__device__ __nv_bfloat16 g_W4t_lo[NPAD4 * HH];

// ---------------------------------------------------------------------------
// Helpers (base-ISA only: cp.async, ldmatrix, mma.sync — all sm_80+)
// ---------------------------------------------------------------------------
__device__ __forceinline__ uint32_t smem_u32(const void* p) {
    uint32_t a;
    asm("{ .reg .u64 t; cvta.to.shared.u64 t, %1; cvt.u32.u64 %0, t; }"
        : "=r"(a) : "l"(p));
    return a;
}

// 64B-row swizzle (SW64 atom: 8 rows x 64B): conflict-free ldmatrix
#define SWZ64(o) ((o) ^ (((o) >> 3) & 0x30))

__device__ __forceinline__ void cp_async16(uint32_t dst, const void* src) {
    asm volatile("cp.async.cg.shared.global [%0], [%1], 16;" :: "r"(dst), "l"(src));
}
__device__ __forceinline__ void cp_commit() {
    asm volatile("cp.async.commit_group;" ::: "memory");
}
__device__ __forceinline__ void cp_wait2() {
    asm volatile("cp.async.wait_group 2;" ::: "memory");
}

__device__ __forceinline__ void ldsm_x4(uint32_t* r, uint32_t addr) {
    asm volatile("ldmatrix.sync.aligned.m8n8.x4.shared.b16 {%0,%1,%2,%3}, [%4];"
                 : "=r"(r[0]), "=r"(r[1]), "=r"(r[2]), "=r"(r[3]) : "r"(addr));
}

__device__ __forceinline__ void mma_bf16(float* d, const uint32_t* a, const uint32_t* b) {
    asm volatile(
        "mma.sync.aligned.m16n8k16.row.col.f32.bf16.bf16.f32 "
        "{%0,%1,%2,%3}, {%4,%5,%6,%7}, {%8,%9}, {%0,%1,%2,%3};"
        : "+f"(d[0]), "+f"(d[1]), "+f"(d[2]), "+f"(d[3])
        : "r"(a[0]), "r"(a[1]), "r"(a[2]), "r"(a[3]), "r"(b[0]), "r"(b[1]));
}

// ---------------------------------------------------------------------------
// mma.sync GEMM: C[2560, Nact] = A[2560,1024] @ Bt[Npad,1024]^T (+bias)
// A, Bt in bf16 hi/lo split (K-major). BM=BN=128, BK=32, 4-stage cp.async.
// 8 warps: warp_m = wid&3 (4), warp_n = wid>>2 (2); warp tile 32 x 64.
// ---------------------------------------------------------------------------
#define GK      HH
#define KSTEPS  (GK / 32)          // 32
#define TILE_B  8192               // one 128x32 bf16 matrix
#define STAGE_B (4 * TILE_B)       // Ahi, Alo, Bhi, Blo
#define NSTAGE  4
#define GSMEM   (NSTAGE * STAGE_B) // 131072

__device__ __forceinline__ void g_load_stage(
    uint32_t sbase, int st, int k0, int tid, int bm, int bn,
    const __nv_bfloat16* __restrict__ Ahi, const __nv_bfloat16* __restrict__ Alo,
    const __nv_bfloat16* __restrict__ Bhi, const __nv_bfloat16* __restrict__ Blo)
{
    uint32_t base = sbase + (st & (NSTAGE - 1)) * STAGE_B;
#pragma unroll
    for (int i = 0; i < 2; i++) {
        int idx = tid + i * 256;           // 512 chunks: 128 rows x 4 chunks
        int row = idx >> 2, ch = idx & 3;
        uint32_t off = SWZ64((uint32_t)(row * 64 + ch * 16));
        size_t ga = (size_t)(bm + row) * GK + k0 + ch * 8;
        size_t gb = (size_t)(bn + row) * GK + k0 + ch * 8;
        cp_async16(base + off,              Ahi + ga);
        cp_async16(base + TILE_B + off,     Alo + ga);
        cp_async16(base + 2 * TILE_B + off, Bhi + gb);
        cp_async16(base + 3 * TILE_B + off, Blo + gb);
    }
}

__global__ __launch_bounds__(256, 1)
void gemm_mma(const __nv_bfloat16* __restrict__ Ahi, const __nv_bfloat16* __restrict__ Alo,
              const __nv_bfloat16* __restrict__ Bhi, const __nv_bfloat16* __restrict__ Blo,
              const float* __restrict__ bias, float* __restrict__ C, int Nact)
{
    extern __shared__ char smem[];
    const uint32_t sbase = smem_u32(smem);
    const int tid = threadIdx.x;
    const int wid = tid >> 5, lane = tid & 31;
    const int warp_m = wid & 3, warp_n = wid >> 2;
    const int bm = blockIdx.y * 128;
    const int bn = blockIdx.x * 128;

    float acc[2][8][4];
#pragma unroll
    for (int i = 0; i < 2; i++)
#pragma unroll
        for (int j = 0; j < 8; j++)
#pragma unroll
            for (int q = 0; q < 4; q++) acc[i][j][q] = 0.f;

    // prologue: load 3 stages
    g_load_stage(sbase, 0, 0, tid, bm, bn, Ahi, Alo, Bhi, Blo); cp_commit();
    g_load_stage(sbase, 1, 32, tid, bm, bn, Ahi, Alo, Bhi, Blo); cp_commit();
    g_load_stage(sbase, 2, 64, tid, bm, bn, Ahi, Alo, Bhi, Blo); cp_commit();

    // per-lane ldmatrix address components (within a 128x32 tile, 64B rows)
    const int a_r = (lane & 7) + ((lane >> 3) & 1) * 8;  // row within 16-tile
    const int a_c = (lane >> 4);                          // k-chunk half
    const int b_r = (lane & 7) + ((lane >> 4) & 1) * 8;
    const int b_c = (lane >> 3) & 1;

    for (int s = 0; s < KSTEPS; s++) {
        cp_wait2();
        __syncthreads();

        if (s + 3 < KSTEPS) {
            g_load_stage(sbase, s + 3, (s + 3) * 32, tid, bm, bn, Ahi, Alo, Bhi, Blo);
        }
        cp_commit();   // uniform group count (empty groups in tail)

        uint32_t stg = sbase + (s & (NSTAGE - 1)) * STAGE_B;
#pragma unroll
        for (int h = 0; h < 2; h++) {      // two k16 halves of BK=32
            uint32_t a_hi[2][4], a_lo[2][4], b_hi[4][4], b_lo[4][4];
#pragma unroll
            for (int mt = 0; mt < 2; mt++) {
                int row = warp_m * 32 + mt * 16 + a_r;
                uint32_t off = SWZ64((uint32_t)(row * 64 + (2 * h + a_c) * 16));
                ldsm_x4(a_hi[mt], stg + off);
                ldsm_x4(a_lo[mt], stg + TILE_B + off);
            }
#pragma unroll
            for (int p = 0; p < 4; p++) {
                int row = warp_n * 64 + p * 16 + b_r;
                uint32_t off = SWZ64((uint32_t)(row * 64 + (2 * h + b_c) * 16));
                ldsm_x4(b_hi[p], stg + 2 * TILE_B + off);
                ldsm_x4(b_lo[p], stg + 3 * TILE_B + off);
            }
#pragma unroll
            for (int mt = 0; mt < 2; mt++)
#pragma unroll
                for (int p = 0; p < 4; p++)
#pragma unroll
                    for (int q = 0; q < 2; q++) {
                        float* d = acc[mt][2 * p + q];
                        mma_bf16(d, a_hi[mt], &b_hi[p][2 * q]);
                        mma_bf16(d, a_hi[mt], &b_lo[p][2 * q]);
                        mma_bf16(d, a_lo[mt], &b_hi[p][2 * q]);
                    }
        }
        __syncthreads();
    }

    // epilogue: c-frag (m16n8): d0,d1 -> (row, col..col+1); d2,d3 -> (row+8, ...)
    const int er = lane >> 2;
    const int ec = (lane & 3) * 2;
    const bool even_stride = (Nact & 1) == 0;
#pragma unroll
    for (int mt = 0; mt < 2; mt++) {
#pragma unroll
        for (int nt = 0; nt < 8; nt++) {
            int row = bm + warp_m * 32 + mt * 16 + er;
            int col = bn + warp_n * 64 + nt * 8 + ec;
            float* d = acc[mt][nt];
            if (even_stride) {
                // even row stride -> 8B-aligned float2 stores (col < Nact here)
                float b0 = bias ? bias[col] : 0.f;
                float b1 = bias ? bias[col + 1] : 0.f;
                *(float2*)(C + (size_t)row * Nact + col) =
                    make_float2(d[0] + b0, d[1] + b1);
                *(float2*)(C + (size_t)(row + 8) * Nact + col) =
                    make_float2(d[2] + b0, d[3] + b1);
            } else {
                // odd stride (logits, Nact=1095): scalar stores + bounds
                if (col < Nact) {
                    float b0 = bias ? bias[col] : 0.f;
                    C[(size_t)row * Nact + col]       = d[0] + b0;
                    C[(size_t)(row + 8) * Nact + col] = d[2] + b0;
                }
                if (col + 1 < Nact) {
                    float b1 = bias ? bias[col + 1] : 0.f;
                    C[(size_t)row * Nact + col + 1]       = d[1] + b1;
                    C[(size_t)(row + 8) * Nact + col + 1] = d[3] + b1;
                }
            }
        }
    }
}

// ---------------------------------------------------------------------------
// Weight transpose + bf16 hi/lo split: out[n][k] = W[k][n]. K = 1024.
// ---------------------------------------------------------------------------
__global__ void transpose_split(const float* __restrict__ W,
                                __nv_bfloat16* __restrict__ hi,
                                __nv_bfloat16* __restrict__ lo,
                                int Nsrc, int Npad)
{
    __shared__ float t[32][33];
    int nb = blockIdx.x * 32, kb = blockIdx.y * 32;
    int tx = threadIdx.x, ty = threadIdx.y;   // 32 x 8
#pragma unroll
    for (int i = ty; i < 32; i += 8) {
        int n = nb + tx;
        t[i][tx] = (n < Nsrc) ? W[(size_t)(kb + i) * Nsrc + n] : 0.f;
    }
    __syncthreads();
#pragma unroll
    for (int i = ty; i < 32; i += 8) {
        int n = nb + i, k = kb + tx;
        if (n < Npad) {
            float v = t[tx][i];
            __nv_bfloat16 h = __float2bfloat16(v);
            hi[(size_t)n * HH + k] = h;
            lo[(size_t)n * HH + k] = __float2bfloat16(v - __bfloat162float(h));
        }
    }
}

// ---------------------------------------------------------------------------
// Activation fp32 -> bf16 hi/lo. PERM 0 identity, PERM 2: [T,B]->[B,T]. RELU opt.
// ---------------------------------------------------------------------------
template<int PERM, bool RELU>
__global__ __launch_bounds__(256)
void convert_act(const float* __restrict__ src,
                 __nv_bfloat16* __restrict__ hi, __nv_bfloat16* __restrict__ lo)
{
    int i = blockIdx.x * blockDim.x + threadIdx.x;
    if (i >= MM * HH) return;
    int m = i >> 10, k = i & 1023;
    int sm = (PERM == 2) ? ((m % TT) * BB + m / TT) : m;
    float v = src[(size_t)sm * HH + k];
    if (RELU) v = fmaxf(v, 0.f);
    __nv_bfloat16 h = __float2bfloat16(v);
    hi[i] = h;
    lo[i] = __float2bfloat16(v - __bfloat162float(h));
}

// ---------------------------------------------------------------------------
// fp32 SGEMM for dense1 (K=200) with fused bf16 split of the output.
// A' row gm reads x row (gm%B)*T + gm/B
// ---------------------------------------------------------------------------
__global__ __launch_bounds__(256)
void sgemm_d1(const float* __restrict__ A, const float* __restrict__ W,
              const float* __restrict__ bias, float* __restrict__ C,
              __nv_bfloat16* __restrict__ Chi, __nv_bfloat16* __restrict__ Clo,
              int M, int N, int K)
{
    const int BM = 128, BN = 128, BK = 8, TM = 8, TN = 8;
    __shared__ float As[BK][BM];
    __shared__ float Bs[BK][BN];
    const int bm = blockIdx.y * BM, bn = blockIdx.x * BN, tid = threadIdx.x;
    const int tx = (tid % 16) * TN, ty = (tid / 16) * TM;
    const int a_row = tid >> 1, a_kof = (tid & 1) * 4;
    const int b_row = tid >> 5, b_col = (tid & 31) * 4;

    int gm = bm + a_row;
    int arow_g = (gm % BB) * TT + gm / BB;
    const float* Aptr = A + (long)arow_g * K + a_kof;

    float acc[TM][TN];
#pragma unroll
    for (int i = 0; i < TM; i++)
#pragma unroll
        for (int j = 0; j < TN; j++) acc[i][j] = 0.f;

    for (int k0 = 0; k0 < K; k0 += BK) {
        float4 av = *(const float4*)(Aptr + k0);
        As[a_kof + 0][a_row] = av.x;
        As[a_kof + 1][a_row] = av.y;
        As[a_kof + 2][a_row] = av.z;
        As[a_kof + 3][a_row] = av.w;
        float4 bv = *(const float4*)(W + (long)(k0 + b_row) * N + bn + b_col);
        *(float4*)&Bs[b_row][b_col] = bv;
        __syncthreads();
#pragma unroll
        for (int kk = 0; kk < BK; kk++) {
            float a_reg[TM], b_reg[TN];
#pragma unroll
            for (int i = 0; i < TM; i++) a_reg[i] = As[kk][ty + i];
#pragma unroll
            for (int j = 0; j < TN; j++) b_reg[j] = Bs[kk][tx + j];
#pragma unroll
            for (int i = 0; i < TM; i++)
#pragma unroll
                for (int j = 0; j < TN; j++)
                    acc[i][j] = fmaf(a_reg[i], b_reg[j], acc[i][j]);
        }
        __syncthreads();
    }
#pragma unroll
    for (int i = 0; i < TM; i++) {
        int row = bm + ty + i;
#pragma unroll
        for (int j = 0; j < TN; j++) {
            int col = bn + tx + j;
            float v = acc[i][j] + bias[col];
            size_t idx = (size_t)row * N + col;
            C[idx] = v;
            __nv_bfloat16 h = __float2bfloat16(v);
            Chi[idx] = h;
            Clo[idx] = __float2bfloat16(v - __bfloat162float(h));
        }
    }
}

// ---------------------------------------------------------------------------
// SRU elementwise scan with fused bf16 split of the layer output.
// ---------------------------------------------------------------------------
__global__ __launch_bounds__(256)
void sru_scan(const float* __restrict__ U, const float* __restrict__ b_l,
              const float* __restrict__ c0, float* __restrict__ h,
              float* __restrict__ c_out,
              __nv_bfloat16* __restrict__ Hhi, __nv_bfloat16* __restrict__ Hlo)
{
    int idx = blockIdx.x * blockDim.x + threadIdx.x;
    if (idx >= BB * HH) return;
    int j = idx & (HH - 1);
    int b = idx >> 10;

    float bf = b_l[j];
    float br = b_l[HH + j];
    float c  = c0[idx];

#pragma unroll
    for (int t = 0; t < TT; t++) {
        long m = (long)t * BB + b;
        const float* u = U + m * (3 * HH);
        float xt   = u[j];
        float fpre = u[HH + j];
        float rpre = u[2 * HH + j];
        float f = 1.f / (1.f + __expf(-(fpre + bf)));
        float r = 1.f / (1.f + __expf(-(rpre + br)));
        long  hi = m * HH + j;
        float xin = h[hi];
        c = f * c + (1.f - f) * xt;
        float hv = r * tanhf(c) + (1.f - r) * xin;
        h[hi] = hv;
        __nv_bfloat16 hb = __float2bfloat16(hv);
        Hhi[hi] = hb;
        Hlo[hi] = __float2bfloat16(hv - __bfloat162float(hb));
    }
    c_out[idx] = c;
}

// ---------------------------------------------------------------------------
// kernel_launch
// ---------------------------------------------------------------------------
extern "C" void kernel_launch(void* const* d_in, const int* in_sizes, int n_in,
                              void* d_out, int out_size)
{
    const float* x      = (const float*)d_in[0];
    const float* hidden = (const float*)d_in[1];
    const float* W1     = (const float*)d_in[2];
    const float* b1     = (const float*)d_in[3];
    const float* sru_W  = (const float*)d_in[4];
    const float* sru_b  = (const float*)d_in[5];
    const float* W3     = (const float*)d_in[6];
    const float* b3     = (const float*)d_in[7];
    const float* W4     = (const float*)d_in[8];
    const float* b4     = (const float*)d_in[9];

    float* out = (float*)d_out;
    float* logits_out = out;                          // [2560, 1095]
    float* fx_out     = out + (size_t)MM * NOUT;      // [2560, 1024]
    float* hid_out    = fx_out + (size_t)MM * HH;     // [12, 128, 1024]

    float *hbuf, *Ubuf;
    __nv_bfloat16 *Ahi, *Alo, *Wth, *Wtl, *W3h, *W3l, *W4h, *W4l;
    cudaGetSymbolAddress((void**)&hbuf, g_h);
    cudaGetSymbolAddress((void**)&Ubuf, g_U);
    cudaGetSymbolAddress((void**)&Ahi, g_Ahi);
    cudaGetSymbolAddress((void**)&Alo, g_Alo);
    cudaGetSymbolAddress((void**)&Wth, g_Wt_hi);
    cudaGetSymbolAddress((void**)&Wtl, g_Wt_lo);
    cudaGetSymbolAddress((void**)&W3h, g_W3t_hi);
    cudaGetSymbolAddress((void**)&W3l, g_W3t_lo);
    cudaGetSymbolAddress((void**)&W4h, g_W4t_hi);
    cudaGetSymbolAddress((void**)&W4l, g_W4t_lo);

    cudaFuncSetAttribute(gemm_mma, cudaFuncAttributeMaxDynamicSharedMemorySize, GSMEM);

    dim3 blk(256);
    dim3 tb(32, 8);

    // 0) weight prep: transpose + hi/lo split -> K-major [N,K] bf16
    for (int l = 0; l < LL; l++) {
        transpose_split<<<dim3(N3H / 32, HH / 32), tb>>>(
            sru_W + (size_t)l * HH * N3H,
            Wth + (size_t)l * N3H * HH, Wtl + (size_t)l * N3H * HH, N3H, N3H);
    }
    transpose_split<<<dim3(HH / 32, HH / 32), tb>>>(W3, W3h, W3l, HH, HH);
    transpose_split<<<dim3(NPAD4 / 32, HH / 32), tb>>>(W4, W4h, W4l, NOUT, NPAD4);

    // 1) dense1 (fp32) with fused split: g_h[T,B,H] = x @ W1 + b1
    sgemm_d1<<<dim3(HH / 128, MM / 128), blk>>>(x, W1, b1, hbuf, Ahi, Alo,
                                                MM, HH, DIN);

    // 2) SRU layers (tensor-core GEMM + scan with fused split)
    for (int l = 0; l < LL; l++) {
        gemm_mma<<<dim3(N3H / 128, MM / 128), blk, GSMEM>>>(
            Ahi, Alo, Wth + (size_t)l * N3H * HH, Wtl + (size_t)l * N3H * HH,
            nullptr, Ubuf, N3H);
        sru_scan<<<(BB * HH) / 256, blk>>>(
            Ubuf, sru_b + (size_t)l * 2 * HH, hidden + (size_t)l * BB * HH,
            hbuf, hid_out + (size_t)l * BB * HH, Ahi, Alo);
    }

    // 3) reorder [T,B]->[B,T] split, then fx = h @ W3 + b3
    convert_act<2, false><<<(MM * HH) / 256, blk>>>(hbuf, Ahi, Alo);
    gemm_mma<<<dim3(HH / 128, MM / 128), blk, GSMEM>>>(
        Ahi, Alo, W3h, W3l, b3, fx_out, HH);

    // 4) logits = relu(fx) @ W4 + b4
    convert_act<0, true><<<(MM * HH) / 256, blk>>>(fx_out, Ahi, Alo);
    gemm_mma<<<dim3(NPAD4 / 128, MM / 128), blk, GSMEM>>>(
        Ahi, Alo, W4h, W4l, b4, logits_out, NOUT);
}

// round 5
// speedup vs baseline: 2.9741x; 1.1583x over previous
#include <cuda_runtime.h>
#include <cuda_bf16.h>
#include <cstdint>
#include <math.h>

// Problem constants
#define BB   128
#define TT   20
#define DIN  200
#define HH   1024
#define LL   12
#define NOUT 1095
#define MM   (BB * TT)      // 2560
#define N3H  (3 * HH)       // 3072
#define NPAD4 1152          // W4 N padded to multiple of 128

// ---------------------------------------------------------------------------
// Scratch (device globals)
// ---------------------------------------------------------------------------
__device__ float g_U[MM * N3H];
__device__ __nv_bfloat16 g_Ahi[MM * HH];     // activations [T,B] order
__device__ __nv_bfloat16 g_Alo[MM * HH];
__device__ __nv_bfloat16 g_Bhi[MM * HH];     // last-layer output, [B,T] order
__device__ __nv_bfloat16 g_Blo[MM * HH];
__device__ __nv_bfloat16 g_Wt_hi[LL * N3H * HH];
__device__ __nv_bfloat16 g_Wt_lo[LL * N3H * HH];
__device__ __nv_bfloat16 g_W3t_hi[HH * HH];
__device__ __nv_bfloat16 g_W3t_lo[HH * HH];
__device__ __nv_bfloat16 g_W4t_hi[NPAD4 * HH];
__device__ __nv_bfloat16 g_W4t_lo[NPAD4 * HH];

// ---------------------------------------------------------------------------
// Helpers (base-ISA: cp.async, ldmatrix, mma.sync)
// ---------------------------------------------------------------------------
__device__ __forceinline__ uint32_t smem_u32(const void* p) {
    uint32_t a;
    asm("{ .reg .u64 t; cvta.to.shared.u64 t, %1; cvt.u32.u64 %0, t; }"
        : "=r"(a) : "l"(p));
    return a;
}

#define SWZ128(o) ((o) ^ (((o) >> 3) & 0x70))

__device__ __forceinline__ void cp_async16(uint32_t dst, const void* src) {
    asm volatile("cp.async.cg.shared.global [%0], [%1], 16;" :: "r"(dst), "l"(src));
}
__device__ __forceinline__ void cp_commit() {
    asm volatile("cp.async.commit_group;" ::: "memory");
}
__device__ __forceinline__ void cp_wait1() {
    asm volatile("cp.async.wait_group 1;" ::: "memory");
}

__device__ __forceinline__ void ldsm_x4(uint32_t* r, uint32_t addr) {
    asm volatile("ldmatrix.sync.aligned.m8n8.x4.shared.b16 {%0,%1,%2,%3}, [%4];"
                 : "=r"(r[0]), "=r"(r[1]), "=r"(r[2]), "=r"(r[3]) : "r"(addr));
}

__device__ __forceinline__ void mma_bf16(float* d, const uint32_t* a, const uint32_t* b) {
    asm volatile(
        "mma.sync.aligned.m16n8k16.row.col.f32.bf16.bf16.f32 "
        "{%0,%1,%2,%3}, {%4,%5,%6,%7}, {%8,%9}, {%0,%1,%2,%3};"
        : "+f"(d[0]), "+f"(d[1]), "+f"(d[2]), "+f"(d[3])
        : "r"(a[0]), "r"(a[1]), "r"(a[2]), "r"(a[3]), "r"(b[0]), "r"(b[1]));
}

// ---------------------------------------------------------------------------
// mma.sync GEMM: C[2560, Nact] = A[2560,1024] @ Bt[Npad,1024]^T (+bias)
// bf16 hi/lo split (3 MMA scheme). BM=BN=128, BK=64, 3-stage cp.async,
// single __syncthreads per stage. Optional fused relu+split output (fx).
// ---------------------------------------------------------------------------
#define GK      HH
#define KSTEPS  (GK / 64)          // 16
#define TILE_B  16384              // 128 rows x 64 k x 2B
#define STAGE_B (4 * TILE_B)       // Ahi, Alo, Bhi, Blo = 64KB
#define NSTAGE  3
#define GSMEM   (NSTAGE * STAGE_B) // 196608

__device__ __forceinline__ void g_load_stage(
    uint32_t sbase, int st, int k0, int tid, int bm, int bn,
    const __nv_bfloat16* __restrict__ Ahi, const __nv_bfloat16* __restrict__ Alo,
    const __nv_bfloat16* __restrict__ Bhi, const __nv_bfloat16* __restrict__ Blo)
{
    uint32_t base = sbase + (st % NSTAGE) * STAGE_B;
#pragma unroll
    for (int p = 0; p < 4; p++) {
        int idx = tid + p * 256;            // 1024 chunks: 128 rows x 8 chunks
        int row = idx >> 3, ch = idx & 7;
        uint32_t off = SWZ128((uint32_t)(row * 128 + ch * 16));
        size_t ga = (size_t)(bm + row) * GK + k0 + ch * 8;
        size_t gb = (size_t)(bn + row) * GK + k0 + ch * 8;
        cp_async16(base + off,              Ahi + ga);
        cp_async16(base + TILE_B + off,     Alo + ga);
        cp_async16(base + 2 * TILE_B + off, Bhi + gb);
        cp_async16(base + 3 * TILE_B + off, Blo + gb);
    }
}

__global__ __launch_bounds__(256, 1)
void gemm_mma(const __nv_bfloat16* __restrict__ Ahi, const __nv_bfloat16* __restrict__ Alo,
              const __nv_bfloat16* __restrict__ Bhi, const __nv_bfloat16* __restrict__ Blo,
              const float* __restrict__ bias, float* __restrict__ C, int Nact,
              __nv_bfloat16* __restrict__ Ohi, __nv_bfloat16* __restrict__ Olo)
{
    extern __shared__ char smem[];
    const uint32_t sbase = smem_u32(smem);
    const int tid = threadIdx.x;
    const int wid = tid >> 5, lane = tid & 31;
    const int warp_m = wid & 3, warp_n = wid >> 2;
    const int bm = blockIdx.y * 128;
    const int bn = blockIdx.x * 128;

    float acc[2][8][4];
#pragma unroll
    for (int i = 0; i < 2; i++)
#pragma unroll
        for (int j = 0; j < 8; j++)
#pragma unroll
            for (int q = 0; q < 4; q++) acc[i][j][q] = 0.f;

    // prologue: 2 stages in flight
    g_load_stage(sbase, 0, 0, tid, bm, bn, Ahi, Alo, Bhi, Blo); cp_commit();
    g_load_stage(sbase, 1, 64, tid, bm, bn, Ahi, Alo, Bhi, Blo); cp_commit();

    // ldmatrix per-lane address components
    const int a_r = (lane & 7) + ((lane >> 3) & 1) * 8;
    const int a_c = (lane >> 4);
    const int b_r = (lane & 7) + ((lane >> 4) & 1) * 8;
    const int b_c = (lane >> 3) & 1;

    for (int s = 0; s < KSTEPS; s++) {
        cp_wait1();          // stage s data ready
        __syncthreads();     // also: all warps finished reading stage s-1

        if (s + 2 < KSTEPS) {
            g_load_stage(sbase, s + 2, (s + 2) * 64, tid, bm, bn, Ahi, Alo, Bhi, Blo);
        }
        cp_commit();         // uniform group count (empty in tail)

        uint32_t stg = sbase + (s % NSTAGE) * STAGE_B;
#pragma unroll
        for (int h = 0; h < 4; h++) {       // four k16 chunks of BK=64
            uint32_t a_hi[2][4], a_lo[2][4], b_hi[4][4], b_lo[4][4];
#pragma unroll
            for (int mt = 0; mt < 2; mt++) {
                int row = warp_m * 32 + mt * 16 + a_r;
                uint32_t off = SWZ128((uint32_t)(row * 128 + h * 32 + a_c * 16));
                ldsm_x4(a_hi[mt], stg + off);
                ldsm_x4(a_lo[mt], stg + TILE_B + off);
            }
#pragma unroll
            for (int p = 0; p < 4; p++) {
                int row = warp_n * 64 + p * 16 + b_r;
                uint32_t off = SWZ128((uint32_t)(row * 128 + h * 32 + b_c * 16));
                ldsm_x4(b_hi[p], stg + 2 * TILE_B + off);
                ldsm_x4(b_lo[p], stg + 3 * TILE_B + off);
            }
#pragma unroll
            for (int mt = 0; mt < 2; mt++)
#pragma unroll
                for (int p = 0; p < 4; p++)
#pragma unroll
                    for (int q = 0; q < 2; q++) {
                        float* d = acc[mt][2 * p + q];
                        mma_bf16(d, a_hi[mt], &b_hi[p][2 * q]);
                        mma_bf16(d, a_hi[mt], &b_lo[p][2 * q]);
                        mma_bf16(d, a_lo[mt], &b_hi[p][2 * q]);
                    }
        }
    }

    // epilogue
    const int er = lane >> 2;
    const int ec = (lane & 3) * 2;
    const bool even_stride = (Nact & 1) == 0;
#pragma unroll
    for (int mt = 0; mt < 2; mt++) {
#pragma unroll
        for (int nt = 0; nt < 8; nt++) {
            int row = bm + warp_m * 32 + mt * 16 + er;
            int col = bn + warp_n * 64 + nt * 8 + ec;
            float* d = acc[mt][nt];
            if (even_stride) {
                float b0 = bias ? bias[col] : 0.f;
                float b1 = bias ? bias[col + 1] : 0.f;
                float v00 = d[0] + b0, v01 = d[1] + b1;
                float v10 = d[2] + b0, v11 = d[3] + b1;
                *(float2*)(C + (size_t)row * Nact + col)       = make_float2(v00, v01);
                *(float2*)(C + (size_t)(row + 8) * Nact + col) = make_float2(v10, v11);
                if (Ohi) {  // fused relu + bf16 hi/lo split (fx path)
                    float r00 = fmaxf(v00, 0.f), r01 = fmaxf(v01, 0.f);
                    float r10 = fmaxf(v10, 0.f), r11 = fmaxf(v11, 0.f);
                    __nv_bfloat16 h00 = __float2bfloat16(r00);
                    __nv_bfloat16 h01 = __float2bfloat16(r01);
                    __nv_bfloat16 h10 = __float2bfloat16(r10);
                    __nv_bfloat16 h11 = __float2bfloat16(r11);
                    size_t i0 = (size_t)row * Nact + col;
                    size_t i1 = (size_t)(row + 8) * Nact + col;
                    *(__nv_bfloat162*)(Ohi + i0) =
                        __nv_bfloat162(h00, h01);
                    *(__nv_bfloat162*)(Ohi + i1) =
                        __nv_bfloat162(h10, h11);
                    *(__nv_bfloat162*)(Olo + i0) = __nv_bfloat162(
                        __float2bfloat16(r00 - __bfloat162float(h00)),
                        __float2bfloat16(r01 - __bfloat162float(h01)));
                    *(__nv_bfloat162*)(Olo + i1) = __nv_bfloat162(
                        __float2bfloat16(r10 - __bfloat162float(h10)),
                        __float2bfloat16(r11 - __bfloat162float(h11)));
                }
            } else {
                // odd stride (logits, Nact=1095): scalar stores + bounds
                if (col < Nact) {
                    float b0 = bias ? bias[col] : 0.f;
                    C[(size_t)row * Nact + col]       = d[0] + b0;
                    C[(size_t)(row + 8) * Nact + col] = d[2] + b0;
                }
                if (col + 1 < Nact) {
                    float b1 = bias ? bias[col + 1] : 0.f;
                    C[(size_t)row * Nact + col + 1]       = d[1] + b1;
                    C[(size_t)(row + 8) * Nact + col + 1] = d[3] + b1;
                }
            }
        }
    }
}

// ---------------------------------------------------------------------------
// Weight transpose + bf16 hi/lo split: out[n][k] = W[k][n], K = 1024.
// 64k x 32n tiles; paired-k bf16x2 (4B) stores.
// ---------------------------------------------------------------------------
__global__ __launch_bounds__(256)
void transpose_split(const float* __restrict__ W,
                     __nv_bfloat16* __restrict__ hi,
                     __nv_bfloat16* __restrict__ lo,
                     int Nsrc, int Npad)
{
    __shared__ float t[64][33];
    int nb = blockIdx.x * 32, kb = blockIdx.y * 64;
    int tx = threadIdx.x & 31;
    int ty = threadIdx.x >> 5;   // 0..7
    int n = nb + tx;
#pragma unroll
    for (int i = 0; i < 8; i++) {
        int kk = ty * 8 + i;
        t[kk][tx] = (n < Nsrc) ? W[(size_t)(kb + kk) * Nsrc + n] : 0.f;
    }
    __syncthreads();
#pragma unroll
    for (int p = 0; p < 4; p++) {
        int idx = threadIdx.x + p * 256;   // 1024 = 32 n x 32 k-pairs
        int nl = idx >> 5, kp = idx & 31;
        float v0 = t[2 * kp][nl];
        float v1 = t[2 * kp + 1][nl];
        __nv_bfloat16 h0 = __float2bfloat16(v0);
        __nv_bfloat16 h1 = __float2bfloat16(v1);
        size_t o = ((size_t)(nb + nl) * HH + kb) / 2 + kp;
        ((__nv_bfloat162*)hi)[o] = __nv_bfloat162(h0, h1);
        ((__nv_bfloat162*)lo)[o] = __nv_bfloat162(
            __float2bfloat16(v0 - __bfloat162float(h0)),
            __float2bfloat16(v1 - __bfloat162float(h1)));
    }
}

// ---------------------------------------------------------------------------
// fp32 SGEMM for dense1 (K=200), writes only bf16 hi/lo split.
// A' row gm reads x row (gm%B)*T + gm/B  ([B,T] -> [T,B])
// ---------------------------------------------------------------------------
__global__ __launch_bounds__(256)
void sgemm_d1(const float* __restrict__ A, const float* __restrict__ W,
              const float* __restrict__ bias,
              __nv_bfloat16* __restrict__ Chi, __nv_bfloat16* __restrict__ Clo,
              int M, int N, int K)
{
    const int BM = 128, BN = 128, BK = 8, TM = 8, TN = 8;
    __shared__ float As[BK][BM];
    __shared__ float Bs[BK][BN];
    const int bm = blockIdx.y * BM, bn = blockIdx.x * BN, tid = threadIdx.x;
    const int tx = (tid % 16) * TN, ty = (tid / 16) * TM;
    const int a_row = tid >> 1, a_kof = (tid & 1) * 4;
    const int b_row = tid >> 5, b_col = (tid & 31) * 4;

    int gm = bm + a_row;
    int arow_g = (gm % BB) * TT + gm / BB;
    const float* Aptr = A + (long)arow_g * K + a_kof;

    float acc[TM][TN];
#pragma unroll
    for (int i = 0; i < TM; i++)
#pragma unroll
        for (int j = 0; j < TN; j++) acc[i][j] = 0.f;

    for (int k0 = 0; k0 < K; k0 += BK) {
        float4 av = *(const float4*)(Aptr + k0);
        As[a_kof + 0][a_row] = av.x;
        As[a_kof + 1][a_row] = av.y;
        As[a_kof + 2][a_row] = av.z;
        As[a_kof + 3][a_row] = av.w;
        float4 bv = *(const float4*)(W + (long)(k0 + b_row) * N + bn + b_col);
        *(float4*)&Bs[b_row][b_col] = bv;
        __syncthreads();
#pragma unroll
        for (int kk = 0; kk < BK; kk++) {
            float a_reg[TM], b_reg[TN];
#pragma unroll
            for (int i = 0; i < TM; i++) a_reg[i] = As[kk][ty + i];
#pragma unroll
            for (int j = 0; j < TN; j++) b_reg[j] = Bs[kk][tx + j];
#pragma unroll
            for (int i = 0; i < TM; i++)
#pragma unroll
                for (int j = 0; j < TN; j++)
                    acc[i][j] = fmaf(a_reg[i], b_reg[j], acc[i][j]);
        }
        __syncthreads();
    }
#pragma unroll
    for (int i = 0; i < TM; i++) {
        int row = bm + ty + i;
#pragma unroll
        for (int j = 0; j < TN; j++) {
            int col = bn + tx + j;
            float v = acc[i][j] + bias[col];
            size_t idx = (size_t)row * N + col;
            __nv_bfloat16 h = __float2bfloat16(v);
            Chi[idx] = h;
            Clo[idx] = __float2bfloat16(v - __bfloat162float(h));
        }
    }
}

// ---------------------------------------------------------------------------
// SRU elementwise scan. xin reconstructed from hi/lo; output written as hi/lo.
// last=0: in-place [T,B] order (Xhi==Ohi). last=1: out row = b*TT + t.
// ---------------------------------------------------------------------------
__global__ __launch_bounds__(256)
void sru_scan(const float* __restrict__ U, const float* __restrict__ b_l,
              const float* __restrict__ c0,
              const __nv_bfloat16* __restrict__ Xhi, const __nv_bfloat16* __restrict__ Xlo,
              __nv_bfloat16* __restrict__ Ohi, __nv_bfloat16* __restrict__ Olo,
              float* __restrict__ c_out, int last)
{
    int idx = blockIdx.x * blockDim.x + threadIdx.x;
    if (idx >= BB * HH) return;
    int j = idx & (HH - 1);
    int b = idx >> 10;

    float bf = b_l[j];
    float br = b_l[HH + j];
    float c  = c0[idx];

#pragma unroll
    for (int t = 0; t < TT; t++) {
        long m = (long)t * BB + b;
        const float* u = U + m * (3 * HH);
        float xt   = u[j];
        float fpre = u[HH + j];
        float rpre = u[2 * HH + j];
        float f = 1.f / (1.f + __expf(-(fpre + bf)));
        float r = 1.f / (1.f + __expf(-(rpre + br)));
        long  xi = m * HH + j;
        float xin = __bfloat162float(Xhi[xi]) + __bfloat162float(Xlo[xi]);
        c = f * c + (1.f - f) * xt;
        float hv = r * tanhf(c) + (1.f - r) * xin;
        long oi = last ? ((long)(b * TT + t) * HH + j) : xi;
        __nv_bfloat16 hb = __float2bfloat16(hv);
        Ohi[oi] = hb;
        Olo[oi] = __float2bfloat16(hv - __bfloat162float(hb));
    }
    c_out[idx] = c;
}

// ---------------------------------------------------------------------------
// kernel_launch
// ---------------------------------------------------------------------------
extern "C" void kernel_launch(void* const* d_in, const int* in_sizes, int n_in,
                              void* d_out, int out_size)
{
    const float* x      = (const float*)d_in[0];
    const float* hidden = (const float*)d_in[1];
    const float* W1     = (const float*)d_in[2];
    const float* b1     = (const float*)d_in[3];
    const float* sru_W  = (const float*)d_in[4];
    const float* sru_b  = (const float*)d_in[5];
    const float* W3     = (const float*)d_in[6];
    const float* b3     = (const float*)d_in[7];
    const float* W4     = (const float*)d_in[8];
    const float* b4     = (const float*)d_in[9];

    float* out = (float*)d_out;
    float* logits_out = out;                          // [2560, 1095]
    float* fx_out     = out + (size_t)MM * NOUT;      // [2560, 1024]
    float* hid_out    = fx_out + (size_t)MM * HH;     // [12, 128, 1024]

    float* Ubuf;
    __nv_bfloat16 *Ahi, *Alo, *Bhi, *Blo, *Wth, *Wtl, *W3h, *W3l, *W4h, *W4l;
    cudaGetSymbolAddress((void**)&Ubuf, g_U);
    cudaGetSymbolAddress((void**)&Ahi, g_Ahi);
    cudaGetSymbolAddress((void**)&Alo, g_Alo);
    cudaGetSymbolAddress((void**)&Bhi, g_Bhi);
    cudaGetSymbolAddress((void**)&Blo, g_Blo);
    cudaGetSymbolAddress((void**)&Wth, g_Wt_hi);
    cudaGetSymbolAddress((void**)&Wtl, g_Wt_lo);
    cudaGetSymbolAddress((void**)&W3h, g_W3t_hi);
    cudaGetSymbolAddress((void**)&W3l, g_W3t_lo);
    cudaGetSymbolAddress((void**)&W4h, g_W4t_hi);
    cudaGetSymbolAddress((void**)&W4l, g_W4t_lo);

    cudaFuncSetAttribute(gemm_mma, cudaFuncAttributeMaxDynamicSharedMemorySize, GSMEM);

    dim3 blk(256);

    // 0) weight prep: transpose + hi/lo split -> K-major [N,K] bf16
    for (int l = 0; l < LL; l++) {
        transpose_split<<<dim3(N3H / 32, HH / 64), blk>>>(
            sru_W + (size_t)l * HH * N3H,
            Wth + (size_t)l * N3H * HH, Wtl + (size_t)l * N3H * HH, N3H, N3H);
    }
    transpose_split<<<dim3(HH / 32, HH / 64), blk>>>(W3, W3h, W3l, HH, HH);
    transpose_split<<<dim3(NPAD4 / 32, HH / 64), blk>>>(W4, W4h, W4l, NOUT, NPAD4);

    // 1) dense1 (fp32): hi/lo split of x @ W1 + b1, [T,B] order
    sgemm_d1<<<dim3(HH / 128, MM / 128), blk>>>(x, W1, b1, Ahi, Alo, MM, HH, DIN);

    // 2) SRU layers
    for (int l = 0; l < LL; l++) {
        gemm_mma<<<dim3(N3H / 128, MM / 128), blk, GSMEM>>>(
            Ahi, Alo, Wth + (size_t)l * N3H * HH, Wtl + (size_t)l * N3H * HH,
            nullptr, Ubuf, N3H, nullptr, nullptr);
        int last = (l == LL - 1);
        sru_scan<<<(BB * HH) / 256, blk>>>(
            Ubuf, sru_b + (size_t)l * 2 * HH, hidden + (size_t)l * BB * HH,
            Ahi, Alo,
            last ? Bhi : Ahi, last ? Blo : Alo,
            hid_out + (size_t)l * BB * HH, last);
    }

    // 3) fx = h([B,T]) @ W3 + b3, with fused relu+split into Ahi/Alo
    gemm_mma<<<dim3(HH / 128, MM / 128), blk, GSMEM>>>(
        Bhi, Blo, W3h, W3l, b3, fx_out, HH, Ahi, Alo);

    // 4) logits = relu(fx) @ W4 + b4
    gemm_mma<<<dim3(NPAD4 / 128, MM / 128), blk, GSMEM>>>(
        Ahi, Alo, W4h, W4l, b4, logits_out, NOUT, nullptr, nullptr);
}